// round 9
// baseline (speedup 1.0000x reference)
#include <cuda_runtime.h>
#include <cuda_fp16.h>
#include <cstdint>
#include <cstddef>

// KMeansLayer via mma.sync m16n8k16 (fp16 2-way split, 3 passes) + fused softmax.
// out[n,k] = softmax_k( 20*(x_n . c_k) - 10*||c_k||^2 )   (||x||^2 cancels)
// x: [32768, 256] f32, centroids: [512, 256] f32, out: [32768, 512] f32.
// R9: A hi/lo split hoisted to a prologue kernel (in-loop A = 4 LDS.128),
//     4-stage pipeline (2 steps of load slack).

#define NRTOT   32768
#define KCLUST  512
#define DDIM    256
#define MT      64          // rows per CTA
#define NK      16          // k16 steps (DDIM/16)
#define NST     4           // pipeline stages
#define NTHR    512
#define LOG2E   1.4426950408889634f

#define A_STG_BYTES 4096    // 2 hl * 4 gmt * 32 lanes * 16B
#define B_STG_BYTES 32768   // 2 hl * 64 nt * 32 lanes * 8B
#define STG_BYTES   (A_STG_BYTES + B_STG_BYTES)          // 36864
#define OFF_C10     (NST * STG_BYTES)                    // 147456
#define OFF_REDM    (OFF_C10 + 2048)
#define OFF_REDS    (OFF_REDM + 2048)
#define SMEM_TOTAL  (OFF_REDS + 2048)                    // 153600

#define XS_STRIDE   260     // aconv staging row stride (floats)

// device scratch
__device__ float g_csq10[KCLUST];
__device__ uint2 g_Bfrag[NK * 2 * 64 * 32];              // 0.5 MB fp16 B frags
__device__ uint4 g_Afrag[(size_t)512 * NK * 2 * 4 * 32]; // 32 MB fp16 A frags

// ---------------------------------------------------------------- helpers
__device__ __forceinline__ uint32_t smem_u32(const void* p) {
    uint32_t a;
    asm("{ .reg .u64 t; cvta.to.shared.u64 t, %1; cvt.u32.u64 %0, t; }"
        : "=r"(a) : "l"(p));
    return a;
}
__device__ __forceinline__ uint32_t packh2(float a, float b) {
    __half2 h = __floats2half2_rn(a, b);
    return *reinterpret_cast<uint32_t*>(&h);
}
__device__ __forceinline__ void cp16(uint32_t dst, const void* src) {
    asm volatile("cp.async.cg.shared.global [%0], [%1], 16;"
                 :: "r"(dst), "l"(__cvta_generic_to_global(src)) : "memory");
}
#define CP_COMMIT() asm volatile("cp.async.commit_group;" ::: "memory")
#define CP_WAIT(n)  asm volatile("cp.async.wait_group %0;" :: "n"(n) : "memory")

__device__ __forceinline__ void mma16(float* d, const uint4& a, const uint2& b) {
    asm("mma.sync.aligned.m16n8k16.row.col.f32.f16.f16.f32 "
        "{%0,%1,%2,%3}, {%4,%5,%6,%7}, {%8,%9}, {%0,%1,%2,%3};"
        : "+f"(d[0]), "+f"(d[1]), "+f"(d[2]), "+f"(d[3])
        : "r"(a.x), "r"(a.y), "r"(a.z), "r"(a.w), "r"(b.x), "r"(b.y));
}

// ------------------------------------------------------ prologue: centroids
// One block per cluster n: 10*||c_n||^2 + fp16 hi/lo B fragments.
__global__ void prep_kernel(const float* __restrict__ cent) {
    __shared__ float cs[DDIM];
    __shared__ float part[64];
    const int n = blockIdx.x, t = threadIdx.x;

    if (t < 64) {
        float4 v = reinterpret_cast<const float4*>(cent)[n * (DDIM / 4) + t];
        reinterpret_cast<float4*>(cs)[t] = v;
        part[t] = v.x * v.x + v.y * v.y + v.z * v.z + v.w * v.w;
    }
    __syncthreads();
    if (t < 32) {
        float s = part[t] + part[t + 32];
#pragma unroll
        for (int o = 16; o > 0; o >>= 1) s += __shfl_xor_sync(0xffffffffu, s, o);
        if (t == 0) g_csq10[n] = 10.0f * s;
    }

    const int kc = t >> 3, hl = (t >> 2) & 1, tig = t & 3;
    const int k0 = kc * 16 + 2 * tig;
    const float v[4] = {cs[k0], cs[k0 + 1], cs[k0 + 8], cs[k0 + 9]};
    uint32_t p0, p1;
    if (hl == 0) {
        p0 = packh2(v[0], v[1]);
        p1 = packh2(v[2], v[3]);
    } else {
        float r[4];
#pragma unroll
        for (int i = 0; i < 4; ++i) {
            __half h = __float2half_rn(v[i]);
            r[i] = v[i] - __half2float(h);
        }
        p0 = packh2(r[0], r[1]);
        p1 = packh2(r[2], r[3]);
    }
    const int nt = n >> 3;
    const int lane = (n & 7) * 4 + tig;
    g_Bfrag[((kc * 2 + hl) * 64 + nt) * 32 + lane] = make_uint2(p0, p1);
}

// ------------------------------------------------------ prologue: x frags
// One block per rowblock (64 rows). Stage x tile in smem (coalesced read),
// emit fp16 hi/lo fragments: [rb][kc 16][hl 2][gmt 4][lane 32] uint4.
__global__ void aconv_kernel(const float* __restrict__ x) {
    extern __shared__ float xs[];                // [64][XS_STRIDE]
    const int rb = blockIdx.x, t = threadIdx.x;  // 256 threads

    const float4* x4 = reinterpret_cast<const float4*>(x) + (size_t)rb * 64 * 64;
    float4* xs4 = reinterpret_cast<float4*>(xs);
#pragma unroll
    for (int i = 0; i < 16; ++i) {
        const int idx = t + i * 256;             // 0..4095
        const int row = idx >> 6, k4 = idx & 63;
        xs4[row * (XS_STRIDE / 4) + k4] = x4[idx];
    }
    __syncthreads();

    const int hl = t >> 7, gmt = (t >> 5) & 3, lane = t & 31;
    const int grp = lane >> 2, tig = lane & 3;
    const int r0 = gmt * 16 + grp;
#pragma unroll
    for (int kc = 0; kc < NK; ++kc) {
        const int k0 = kc * 16 + 2 * tig;
        const float2 p0 = *reinterpret_cast<const float2*>(&xs[(r0 + 0) * XS_STRIDE + k0]);
        const float2 p1 = *reinterpret_cast<const float2*>(&xs[(r0 + 8) * XS_STRIDE + k0]);
        const float2 p2 = *reinterpret_cast<const float2*>(&xs[(r0 + 0) * XS_STRIDE + k0 + 8]);
        const float2 p3 = *reinterpret_cast<const float2*>(&xs[(r0 + 8) * XS_STRIDE + k0 + 8]);
        const float2 p[4] = {p0, p1, p2, p3};
        uint32_t rg[4];
        if (hl == 0) {
#pragma unroll
            for (int r = 0; r < 4; ++r) rg[r] = packh2(p[r].x, p[r].y);
        } else {
#pragma unroll
            for (int r = 0; r < 4; ++r) {
                __half hx = __float2half_rn(p[r].x);
                __half hy = __float2half_rn(p[r].y);
                rg[r] = packh2(p[r].x - __half2float(hx),
                               p[r].y - __half2float(hy));
            }
        }
        g_Afrag[(((size_t)(rb * NK + kc) * 2 + hl) * 4 + gmt) * 32 + lane] =
            make_uint4(rg[0], rg[1], rg[2], rg[3]);
    }
}

// ------------------------------------------------------------ main kernel
// stage slot: [A frags 4KB][B frags 32KB]
__device__ __forceinline__ void issue_stage(uint32_t sb, int s, int kc,
                                            int rowblk, int tid) {
    const uint32_t dst0 = sb + s * STG_BYTES;
    if (tid < 256) {
        const char* gA = reinterpret_cast<const char*>(g_Afrag) +
                         ((size_t)(rowblk * NK + kc) * 256 + tid) * 16;
        cp16(dst0 + tid * 16, gA);
    }
    const char* gB = reinterpret_cast<const char*>(g_Bfrag) +
                     (size_t)kc * B_STG_BYTES;
#pragma unroll
    for (int j = 0; j < 4; ++j) {
        const int o = (tid + j * NTHR) * 16;
        cp16(dst0 + A_STG_BYTES + o, gB + o);
    }
}

__global__ __launch_bounds__(NTHR, 1)
void kmeans_mma(float* __restrict__ out) {
    extern __shared__ char smem[];
    const uint32_t sb = smem_u32(smem);
    const int tid = threadIdx.x;
    const int w = tid >> 5, lane = tid & 31;
    const int mw = w >> 3, nw = w & 7;       // warp tile: rows mw*32+, cols nw*64+
    const int grp = lane >> 2, tig = lane & 3;
    const int rowblk = blockIdx.x;

    float* c10s = reinterpret_cast<float*>(smem + OFF_C10);
    for (int i = tid; i < KCLUST; i += NTHR) c10s[i] = g_csq10[i];

    float acc[2][8][4];
#pragma unroll
    for (int mt = 0; mt < 2; ++mt)
#pragma unroll
        for (int nt = 0; nt < 8; ++nt)
#pragma unroll
            for (int r = 0; r < 4; ++r) acc[mt][nt][r] = 0.f;

    // pipeline prologue: fill 3 of 4 stages
#pragma unroll
    for (int s = 0; s < 3; ++s) {
        issue_stage(sb, s, s, rowblk, tid);
        CP_COMMIT();
    }
    CP_WAIT(2);
    __syncthreads();

    int sl = 0;
    for (int k = 0; k < NK; ++k) {
        // issue stage k+3 into slot (k+3)%4 == (k-1)%4 — freed by the
        // end-of-step-(k-1) barrier.
        if (k + 3 < NK) {
            int s3 = sl + 3;
            if (s3 >= NST) s3 -= NST;
            issue_stage(sb, s3, k + 3, rowblk, tid);
            CP_COMMIT();
        }

        const char* sA = smem + sl * STG_BYTES;
        const char* sB = sA + A_STG_BYTES;

        // ---- A: 4x LDS.128, pre-split fragments ----
        uint4 ah[2], al[2];
#pragma unroll
        for (int mt = 0; mt < 2; ++mt) {
            const int gmt = mw * 2 + mt;
            ah[mt] = *reinterpret_cast<const uint4*>(
                sA + (((0 * 4 + gmt) * 32 + lane) << 4));
            al[mt] = *reinterpret_cast<const uint4*>(
                sA + (((1 * 4 + gmt) * 32 + lane) << 4));
        }

        // ---- B chunks of 4 n-tiles; pass-major MMA ----
#pragma unroll
        for (int nc = 0; nc < 2; ++nc) {
            uint2 bh[4], bl[4];
#pragma unroll
            for (int j = 0; j < 4; ++j) {
                const int gnt = nw * 8 + nc * 4 + j;
                bh[j] = *reinterpret_cast<const uint2*>(
                    sB + (((0 * 64 + gnt) * 32 + lane) << 3));
                bl[j] = *reinterpret_cast<const uint2*>(
                    sB + (((1 * 64 + gnt) * 32 + lane) << 3));
            }
#pragma unroll
            for (int j = 0; j < 4; ++j) {           // hi*hi
                mma16(acc[0][nc * 4 + j], ah[0], bh[j]);
                mma16(acc[1][nc * 4 + j], ah[1], bh[j]);
            }
#pragma unroll
            for (int j = 0; j < 4; ++j) {           // hi*lo
                mma16(acc[0][nc * 4 + j], ah[0], bl[j]);
                mma16(acc[1][nc * 4 + j], ah[1], bl[j]);
            }
#pragma unroll
            for (int j = 0; j < 4; ++j) {           // lo*hi
                mma16(acc[0][nc * 4 + j], al[0], bh[j]);
                mma16(acc[1][nc * 4 + j], al[1], bh[j]);
            }
        }

        // end of step: stage k+1 must have landed before the next iteration.
        if (k < NK - 3)       CP_WAIT(2);
        else if (k == NK - 3) CP_WAIT(1);
        else if (k == NK - 2) CP_WAIT(0);
        if (k < NK - 1) __syncthreads();
        if (++sl == NST) sl = 0;
    }

    // ---------------- fused softmax epilogue ----------------
#pragma unroll
    for (int mt = 0; mt < 2; ++mt)
#pragma unroll
        for (int nt = 0; nt < 8; ++nt)
#pragma unroll
            for (int r = 0; r < 4; ++r) {
                const int col = nw * 64 + nt * 8 + 2 * tig + (r & 1);
                acc[mt][nt][r] = 20.f * acc[mt][nt][r] - c10s[col];
            }

    float* redM = reinterpret_cast<float*>(smem + OFF_REDM);
    float* redS = reinterpret_cast<float*>(smem + OFF_REDS);

    float mloc[4];
#pragma unroll
    for (int rid = 0; rid < 4; ++rid) {
        const int mt = rid >> 1, rh = rid & 1;
        float m = -1e30f;
#pragma unroll
        for (int nt = 0; nt < 8; ++nt) {
            m = fmaxf(m, acc[mt][nt][rh * 2 + 0]);
            m = fmaxf(m, acc[mt][nt][rh * 2 + 1]);
        }
        m = fmaxf(m, __shfl_xor_sync(0xffffffffu, m, 1));
        m = fmaxf(m, __shfl_xor_sync(0xffffffffu, m, 2));
        float s = 0.f;
#pragma unroll
        for (int nt = 0; nt < 8; ++nt) {
#pragma unroll
            for (int c = 0; c < 2; ++c) {
                const float e = exp2f((acc[mt][nt][rh * 2 + c] - m) * LOG2E);
                acc[mt][nt][rh * 2 + c] = e;     // reuse regs as exp values
                s += e;
            }
        }
        s += __shfl_xor_sync(0xffffffffu, s, 1);
        s += __shfl_xor_sync(0xffffffffu, s, 2);
        mloc[rid] = m;
        if (tig == 0) {
            const int row = mw * 32 + mt * 16 + rh * 8 + grp;
            redM[row * 8 + nw] = m;
            redS[row * 8 + nw] = s;
        }
    }
    __syncthreads();

#pragma unroll
    for (int rid = 0; rid < 4; ++rid) {
        const int mt = rid >> 1, rh = rid & 1;
        const int row = mw * 32 + mt * 16 + rh * 8 + grp;
        float M = -1e30f;
        float mv[8];
#pragma unroll
        for (int j = 0; j < 8; ++j) {
            mv[j] = redM[row * 8 + j];
            M = fmaxf(M, mv[j]);
        }
        float S = 0.f;
#pragma unroll
        for (int j = 0; j < 8; ++j)
            S += redS[row * 8 + j] * exp2f((mv[j] - M) * LOG2E);
        const float scale = exp2f((mloc[rid] - M) * LOG2E) / S;

        float* orow = out + (size_t)(rowblk * MT + row) * KCLUST + nw * 64;
#pragma unroll
        for (int nt = 0; nt < 8; ++nt) {
            float2 v;
            v.x = acc[mt][nt][rh * 2 + 0] * scale;
            v.y = acc[mt][nt][rh * 2 + 1] * scale;
            *reinterpret_cast<float2*>(orow + nt * 8 + 2 * tig) = v;
        }
    }
}

// ---------------------------------------------------------------- launch
extern "C" void kernel_launch(void* const* d_in, const int* in_sizes, int n_in,
                              void* d_out, int out_size) {
    const float* x = (const float*)d_in[0];
    const float* cent = (const float*)d_in[1];
    if (n_in >= 2 && in_sizes[0] == KCLUST * DDIM && in_sizes[1] == NRTOT * DDIM) {
        const float* t = x; x = cent; cent = t;
    }
    float* out = (float*)d_out;

    cudaFuncSetAttribute(kmeans_mma,
                         cudaFuncAttributeMaxDynamicSharedMemorySize,
                         SMEM_TOTAL);
    cudaFuncSetAttribute(aconv_kernel,
                         cudaFuncAttributeMaxDynamicSharedMemorySize,
                         64 * XS_STRIDE * 4);

    prep_kernel<<<KCLUST, 128>>>(cent);
    aconv_kernel<<<NRTOT / MT, 256, 64 * XS_STRIDE * 4>>>(x);
    kmeans_mma<<<NRTOT / MT, NTHR, SMEM_TOTAL>>>(out);
}

// round 10
// speedup vs baseline: 1.2829x; 1.2829x over previous
#include <cuda_runtime.h>
#include <cuda_fp16.h>
#include <cstdint>
#include <cstddef>

// KMeansLayer via mma.sync m16n8k16 (fp16 2-way split, 3 passes) + fused softmax.
// out[n,k] = softmax_k( 20*(x_n . c_k) - 10*||c_k||^2 )   (||x||^2 cancels)
// x: [32768, 256] f32, centroids: [512, 256] f32, out: [32768, 512] f32.
// R10: MT=32 / 256-thread CTAs with __launch_bounds__(256,2) -> 2 resident
//      CTAs per SM (cross-CTA latency hiding). In-loop A split (aconv removed).

#define NRTOT   32768
#define KCLUST  512
#define DDIM    256
#define MT      32          // rows per CTA
#define NK      16          // k16 steps (DDIM/16)
#define NST     3           // pipeline stages
#define NTHR    256
#define LOG2E   1.4426950408889634f

#define A_ROW_F     20      // padded A row stride in floats (80B, 16B-aligned)
#define A_STG_BYTES (MT * A_ROW_F * 4)                   // 2560
#define B_STG_BYTES 32768   // 2 hl * 64 nt * 32 lanes * 8B
#define STG_BYTES   (A_STG_BYTES + B_STG_BYTES)          // 35328
#define OFF_C10     (NST * STG_BYTES)                    // 105984
#define OFF_REDM    (OFF_C10 + 2048)
#define OFF_REDS    (OFF_REDM + 1024)                    // 32 rows * 8 nw * 4B
#define SMEM_TOTAL  (OFF_REDS + 1024)                    // 110080 (x2 = 220KB/SM)

// device scratch
__device__ float g_csq10[KCLUST];
__device__ uint2 g_Bfrag[NK * 2 * 64 * 32];              // 0.5 MB fp16 B frags

// ---------------------------------------------------------------- helpers
__device__ __forceinline__ uint32_t smem_u32(const void* p) {
    uint32_t a;
    asm("{ .reg .u64 t; cvta.to.shared.u64 t, %1; cvt.u32.u64 %0, t; }"
        : "=r"(a) : "l"(p));
    return a;
}
__device__ __forceinline__ uint32_t packh2(float a, float b) {
    __half2 h = __floats2half2_rn(a, b);
    return *reinterpret_cast<uint32_t*>(&h);
}
__device__ __forceinline__ void cp16(uint32_t dst, const void* src) {
    asm volatile("cp.async.cg.shared.global [%0], [%1], 16;"
                 :: "r"(dst), "l"(__cvta_generic_to_global(src)) : "memory");
}
#define CP_COMMIT() asm volatile("cp.async.commit_group;" ::: "memory")
#define CP_WAIT(n)  asm volatile("cp.async.wait_group %0;" :: "n"(n) : "memory")

__device__ __forceinline__ void mma16(float* d, const uint4& a, const uint2& b) {
    asm("mma.sync.aligned.m16n8k16.row.col.f32.f16.f16.f32 "
        "{%0,%1,%2,%3}, {%4,%5,%6,%7}, {%8,%9}, {%0,%1,%2,%3};"
        : "+f"(d[0]), "+f"(d[1]), "+f"(d[2]), "+f"(d[3])
        : "r"(a.x), "r"(a.y), "r"(a.z), "r"(a.w), "r"(b.x), "r"(b.y));
}

// ------------------------------------------------------ prologue: centroids
// One block per cluster n: 10*||c_n||^2 + fp16 hi/lo B fragments.
__global__ void prep_kernel(const float* __restrict__ cent) {
    __shared__ float cs[DDIM];
    __shared__ float part[64];
    const int n = blockIdx.x, t = threadIdx.x;

    if (t < 64) {
        float4 v = reinterpret_cast<const float4*>(cent)[n * (DDIM / 4) + t];
        reinterpret_cast<float4*>(cs)[t] = v;
        part[t] = v.x * v.x + v.y * v.y + v.z * v.z + v.w * v.w;
    }
    __syncthreads();
    if (t < 32) {
        float s = part[t] + part[t + 32];
#pragma unroll
        for (int o = 16; o > 0; o >>= 1) s += __shfl_xor_sync(0xffffffffu, s, o);
        if (t == 0) g_csq10[n] = 10.0f * s;
    }

    const int kc = t >> 3, hl = (t >> 2) & 1, tig = t & 3;
    const int k0 = kc * 16 + 2 * tig;
    const float v[4] = {cs[k0], cs[k0 + 1], cs[k0 + 8], cs[k0 + 9]};
    uint32_t p0, p1;
    if (hl == 0) {
        p0 = packh2(v[0], v[1]);
        p1 = packh2(v[2], v[3]);
    } else {
        float r[4];
#pragma unroll
        for (int i = 0; i < 4; ++i) {
            __half h = __float2half_rn(v[i]);
            r[i] = v[i] - __half2float(h);
        }
        p0 = packh2(r[0], r[1]);
        p1 = packh2(r[2], r[3]);
    }
    const int nt = n >> 3;
    const int lane = (n & 7) * 4 + tig;
    g_Bfrag[((kc * 2 + hl) * 64 + nt) * 32 + lane] = make_uint2(p0, p1);
}

// ------------------------------------------------------------ main kernel
// stage slot: [A raw: 32 rows x 16 floats @ stride 20][B frags: 32KB]
__device__ __forceinline__ void issue_stage(uint32_t sb, int s, int kc,
                                            const float* __restrict__ x,
                                            int rowblk, int tid) {
    const uint32_t dst0 = sb + s * STG_BYTES;
    if (tid < 128) {
        const int row = tid >> 2, part = tid & 3;
        const float* src = x + (size_t)(rowblk * MT + row) * DDIM + kc * 16 + part * 4;
        cp16(dst0 + row * (A_ROW_F * 4) + part * 16, src);
    }
    const char* gB = reinterpret_cast<const char*>(g_Bfrag) +
                     (size_t)kc * B_STG_BYTES;
#pragma unroll
    for (int j = 0; j < 8; ++j) {
        const int o = (tid + j * NTHR) * 16;
        cp16(dst0 + A_STG_BYTES + o, gB + o);
    }
}

__global__ __launch_bounds__(NTHR, 2)
void kmeans_mma(const float* __restrict__ x, float* __restrict__ out) {
    extern __shared__ char smem[];
    const uint32_t sb = smem_u32(smem);
    const int tid = threadIdx.x;
    const int nw = tid >> 5, lane = tid & 31;      // 8 warps, all cover rows 0..31
    const int grp = lane >> 2, tig = lane & 3;
    const int rowblk = blockIdx.x;

    float* c10s = reinterpret_cast<float*>(smem + OFF_C10);
    for (int i = tid; i < KCLUST; i += NTHR) c10s[i] = g_csq10[i];

    float acc[2][8][4];
#pragma unroll
    for (int mt = 0; mt < 2; ++mt)
#pragma unroll
        for (int nt = 0; nt < 8; ++nt)
#pragma unroll
            for (int r = 0; r < 4; ++r) acc[mt][nt][r] = 0.f;

    // pipeline prologue: fill 2 of 3 stages
    issue_stage(sb, 0, 0, x, rowblk, tid);
    CP_COMMIT();
    issue_stage(sb, 1, 1, x, rowblk, tid);
    CP_COMMIT();
    CP_WAIT(1);
    __syncthreads();

    int sl = 0;
    for (int k = 0; k < NK; ++k) {
        // issue stage k+2 into slot (k+2)%3 == (k-1)%3 — freed by the
        // end-of-step-(k-1) barrier.
        if (k + 2 < NK) {
            int s2 = sl + 2;
            if (s2 >= NST) s2 -= NST;
            issue_stage(sb, s2, k + 2, x, rowblk, tid);
            CP_COMMIT();
        }

        const float* sAf = reinterpret_cast<const float*>(smem + sl * STG_BYTES);
        const char*  sB  = smem + sl * STG_BYTES + A_STG_BYTES;

        // ---- A: load raw f32, split into fp16 hi/lo fragments in registers ----
        uint4 ah[2], al[2];
#pragma unroll
        for (int mt = 0; mt < 2; ++mt) {
            const int R0 = mt * 16 + grp;
            float2 p[4];
            p[0] = *reinterpret_cast<const float2*>(&sAf[(R0 + 0) * A_ROW_F + 2 * tig]);
            p[1] = *reinterpret_cast<const float2*>(&sAf[(R0 + 8) * A_ROW_F + 2 * tig]);
            p[2] = *reinterpret_cast<const float2*>(&sAf[(R0 + 0) * A_ROW_F + 2 * tig + 8]);
            p[3] = *reinterpret_cast<const float2*>(&sAf[(R0 + 8) * A_ROW_F + 2 * tig + 8]);
            uint32_t hreg[4], lreg[4];
#pragma unroll
            for (int r = 0; r < 4; ++r) {
                __half hx = __float2half_rn(p[r].x);
                __half hy = __float2half_rn(p[r].y);
                const float rx = p[r].x - __half2float(hx);
                const float ry = p[r].y - __half2float(hy);
                __half2 hh = __halves2half2(hx, hy);
                hreg[r] = *reinterpret_cast<uint32_t*>(&hh);
                lreg[r] = packh2(rx, ry);
            }
            ah[mt] = make_uint4(hreg[0], hreg[1], hreg[2], hreg[3]);
            al[mt] = make_uint4(lreg[0], lreg[1], lreg[2], lreg[3]);
        }

        // ---- B chunks of 4 n-tiles; pass-major MMA ----
#pragma unroll
        for (int nc = 0; nc < 2; ++nc) {
            uint2 bh[4], bl[4];
#pragma unroll
            for (int j = 0; j < 4; ++j) {
                const int gnt = nw * 8 + nc * 4 + j;
                bh[j] = *reinterpret_cast<const uint2*>(
                    sB + (((0 * 64 + gnt) * 32 + lane) << 3));
                bl[j] = *reinterpret_cast<const uint2*>(
                    sB + (((1 * 64 + gnt) * 32 + lane) << 3));
            }
#pragma unroll
            for (int j = 0; j < 4; ++j) {           // hi*hi
                mma16(acc[0][nc * 4 + j], ah[0], bh[j]);
                mma16(acc[1][nc * 4 + j], ah[1], bh[j]);
            }
#pragma unroll
            for (int j = 0; j < 4; ++j) {           // hi*lo
                mma16(acc[0][nc * 4 + j], ah[0], bl[j]);
                mma16(acc[1][nc * 4 + j], ah[1], bl[j]);
            }
#pragma unroll
            for (int j = 0; j < 4; ++j) {           // lo*hi
                mma16(acc[0][nc * 4 + j], al[0], bh[j]);
                mma16(acc[1][nc * 4 + j], al[1], bh[j]);
            }
        }

        // end of step: stage k+1 must have landed before the next iteration.
        if (k < NK - 2) {
            CP_WAIT(1);
            __syncthreads();
        } else if (k == NK - 2) {
            CP_WAIT(0);
            __syncthreads();
        }
        if (++sl == NST) sl = 0;
    }

    // ---------------- fused softmax epilogue ----------------
#pragma unroll
    for (int mt = 0; mt < 2; ++mt)
#pragma unroll
        for (int nt = 0; nt < 8; ++nt)
#pragma unroll
            for (int r = 0; r < 4; ++r) {
                const int col = nw * 64 + nt * 8 + 2 * tig + (r & 1);
                acc[mt][nt][r] = 20.f * acc[mt][nt][r] - c10s[col];
            }

    float* redM = reinterpret_cast<float*>(smem + OFF_REDM);
    float* redS = reinterpret_cast<float*>(smem + OFF_REDS);

    float mloc[4];
#pragma unroll
    for (int rid = 0; rid < 4; ++rid) {
        const int mt = rid >> 1, rh = rid & 1;
        float m = -1e30f;
#pragma unroll
        for (int nt = 0; nt < 8; ++nt) {
            m = fmaxf(m, acc[mt][nt][rh * 2 + 0]);
            m = fmaxf(m, acc[mt][nt][rh * 2 + 1]);
        }
        m = fmaxf(m, __shfl_xor_sync(0xffffffffu, m, 1));
        m = fmaxf(m, __shfl_xor_sync(0xffffffffu, m, 2));
        float s = 0.f;
#pragma unroll
        for (int nt = 0; nt < 8; ++nt) {
#pragma unroll
            for (int c = 0; c < 2; ++c) {
                const float e = exp2f((acc[mt][nt][rh * 2 + c] - m) * LOG2E);
                acc[mt][nt][rh * 2 + c] = e;     // reuse regs as exp values
                s += e;
            }
        }
        s += __shfl_xor_sync(0xffffffffu, s, 1);
        s += __shfl_xor_sync(0xffffffffu, s, 2);
        mloc[rid] = m;
        if (tig == 0) {
            const int row = mt * 16 + rh * 8 + grp;
            redM[row * 8 + nw] = m;
            redS[row * 8 + nw] = s;
        }
    }
    __syncthreads();

#pragma unroll
    for (int rid = 0; rid < 4; ++rid) {
        const int mt = rid >> 1, rh = rid & 1;
        const int row = mt * 16 + rh * 8 + grp;
        float M = -1e30f;
        float mv[8];
#pragma unroll
        for (int j = 0; j < 8; ++j) {
            mv[j] = redM[row * 8 + j];
            M = fmaxf(M, mv[j]);
        }
        float S = 0.f;
#pragma unroll
        for (int j = 0; j < 8; ++j)
            S += redS[row * 8 + j] * exp2f((mv[j] - M) * LOG2E);
        const float scale = exp2f((mloc[rid] - M) * LOG2E) / S;

        float* orow = out + (size_t)(rowblk * MT + row) * KCLUST + nw * 64;
#pragma unroll
        for (int nt = 0; nt < 8; ++nt) {
            float2 v;
            v.x = acc[mt][nt][rh * 2 + 0] * scale;
            v.y = acc[mt][nt][rh * 2 + 1] * scale;
            *reinterpret_cast<float2*>(orow + nt * 8 + 2 * tig) = v;
        }
    }
}

// ---------------------------------------------------------------- launch
extern "C" void kernel_launch(void* const* d_in, const int* in_sizes, int n_in,
                              void* d_out, int out_size) {
    const float* x = (const float*)d_in[0];
    const float* cent = (const float*)d_in[1];
    if (n_in >= 2 && in_sizes[0] == KCLUST * DDIM && in_sizes[1] == NRTOT * DDIM) {
        const float* t = x; x = cent; cent = t;
    }
    float* out = (float*)d_out;

    cudaFuncSetAttribute(kmeans_mma,
                         cudaFuncAttributeMaxDynamicSharedMemorySize,
                         SMEM_TOTAL);

    prep_kernel<<<KCLUST, 128>>>(cent);
    kmeans_mma<<<NRTOT / MT, NTHR, SMEM_TOTAL>>>(x, out);
}